// round 1
// baseline (speedup 1.0000x reference)
#include <cuda_runtime.h>
#include <cuda_bf16.h>

// Problem constants (fixed shapes for this problem)
#define T_LEN 1024
#define N_BATCH 256
#define C_CLASS 128
#define S_TGT 128
#define L_EXT 257          // 2*S+1
#define NEGV -1e30f

// Per-batch partial losses (loss_n / target_len_n). Device global = allowed scratch.
__device__ float g_partial[N_BATCH];

// One CTA per batch item. Threads 0..256 own extended-target states; threads
// 0..127 also double as the log-prob row loaders (register-prefetch double buffer).
__global__ void __launch_bounds__(288, 4) ctc_alpha_kernel(
    const float* __restrict__ log_probs,     // (T, N, C)
    const int*   __restrict__ targets,       // (N, S)
    const int*   __restrict__ input_lengths, // (N,)
    const int*   __restrict__ target_lengths)// (N,)
{
    __shared__ float lpbuf[2][C_CLASS];      // double-buffered log-prob row for this n
    __shared__ float abuf[2][L_EXT + 2];     // alpha double buffer, 2-slot NEG pad at front

    const int n   = blockIdx.x;
    const int tid = threadIdx.x;
    const float* lp = log_probs + (size_t)n * C_CLASS;  // row t at + t*N*C
    const int inLen = input_lengths[n];

    // Per-state constants: ext symbol and skip-transition flag
    int  e    = 0;
    bool skip = false;
    if (tid < L_EXT) {
        if (tid & 1) {
            e = targets[n * S_TGT + (tid >> 1)];
            if (tid >= 3)
                skip = (e != targets[n * S_TGT + ((tid - 2) >> 1)]);
        }
    }

    // Front pad stays NEG forever (writes below target index tid+2 >= 2)
    if (tid < 2) { abuf[0][tid] = NEGV; abuf[1][tid] = NEGV; }

    // Load row t=0
    if (tid < C_CLASS) lpbuf[0][tid] = lp[tid];
    __syncthreads();

    // alpha0: state 0 = lp0[blank], state 1 = lp0[tgt0], rest NEG
    if (tid < L_EXT) {
        float a = NEGV;
        if (tid == 0)      a = lpbuf[0][0];
        else if (tid == 1) a = lpbuf[0][e];
        abuf[0][tid + 2] = a;
    }

    // Load row t=1 into lpbuf[1]; prefetch row t=2 into register
    float r = 0.0f;
    if (tid < C_CLASS) {
        lpbuf[1][tid] = lp[(size_t)1 * N_BATCH * C_CLASS + tid];
        r = lp[(size_t)2 * N_BATCH * C_CLASS + tid];
    }
    __syncthreads();

    int cur = 0;
    #pragma unroll 4
    for (int t = 1; t < T_LEN; ++t) {
        const float* lpc = lpbuf[t & 1];     // row t
        const float* sA  = abuf[cur];        // alpha_{t-1}
        float*       sB  = abuf[cur ^ 1];    // alpha_t

        if (tid < L_EXT) {
            float a0 = sA[tid + 2];
            float a1 = sA[tid + 1];
            float a2 = skip ? sA[tid] : NEGV;
            float m  = fmaxf(a0, fmaxf(a1, a2));
            float s  = __expf(a0 - m) + __expf(a1 - m) + __expf(a2 - m);
            float nv = lpc[e] + m + __logf(s);
            // freeze alpha once t >= input_length
            sB[tid + 2] = (t < inLen) ? nv : a0;
        }
        if (tid < C_CLASS) {
            lpbuf[(t + 1) & 1][tid] = r;     // stage row t+1 (prefetched last iter)
            int t2 = t + 2;
            if (t2 < T_LEN)
                r = lp[(size_t)t2 * N_BATCH * C_CLASS + tid];  // prefetch row t+2
        }
        __syncthreads();
        cur ^= 1;
    }

    if (tid == 0) {
        int tl  = target_lengths[n];
        int idx = 2 * tl;
        float a = abuf[cur][idx + 2];
        float b = abuf[cur][idx + 1];
        float m = fmaxf(a, b);
        float loss = -(m + __logf(__expf(a - m) + __expf(b - m)));
        g_partial[n] = loss / (float)tl;
    }
}

// Deterministic fixed-order tree reduction of the 256 partials -> scalar mean.
__global__ void ctc_reduce_kernel(float* __restrict__ out)
{
    __shared__ float s[N_BATCH];
    int tid = threadIdx.x;
    s[tid] = g_partial[tid];
    __syncthreads();
    #pragma unroll
    for (int st = N_BATCH / 2; st > 0; st >>= 1) {
        if (tid < st) s[tid] += s[tid + st];
        __syncthreads();
    }
    if (tid == 0) out[0] = s[0] * (1.0f / (float)N_BATCH);
}

extern "C" void kernel_launch(void* const* d_in, const int* in_sizes, int n_in,
                              void* d_out, int out_size)
{
    const float* log_probs      = (const float*)d_in[0];
    const int*   targets        = (const int*)  d_in[1];
    const int*   input_lengths  = (const int*)  d_in[2];
    const int*   target_lengths = (const int*)  d_in[3];
    float*       out            = (float*)d_out;

    ctc_alpha_kernel<<<N_BATCH, 288>>>(log_probs, targets, input_lengths, target_lengths);
    ctc_reduce_kernel<<<1, N_BATCH>>>(out);
}

// round 4
// speedup vs baseline: 1.3615x; 1.3615x over previous
#include <cuda_runtime.h>

// Shapes fixed for this problem
#define T_LEN   1024
#define NB      256
#define C_CLASS 128
#define S_TGT   128
#define NEGV    -1e30f
#define LNB     2.0f            // per-step boost (bounded: P <= e^2)
#define PF      16              // prefetch depth (rows ahead)
#define FULLM   0xffffffffu
#define SLACK   12.0f           // max frame drop per lane step (bounds f <= e^12)

__device__ float        g_partial[NB];
__device__ unsigned int g_count;   // zero-init; reset by the reducing CTA each run

// One warp per batch item. 257 extended states in registers:
// lane holds states 8*lane..8*lane+7; lane 31 also state 256 (a8).
// Linear domain, PER-LANE log-scale ls with bounded-slack frame scan.
__global__ void __launch_bounds__(32) ctc_kernel(
    const float* __restrict__ log_probs,      // (T, N, C)
    const int*   __restrict__ targets,        // (N, S)
    const int*   __restrict__ input_lengths,  // (N,)
    const int*   __restrict__ target_lengths, // (N,)
    float*       __restrict__ out)
{
    __shared__ float        sh[257];
    __shared__ unsigned int ticket;

    const int n    = blockIdx.x;
    const int lane = threadIdx.x;
    const float* lpn = log_probs + (size_t)n * C_CLASS;
    const int inLen  = input_lengths[n];

    // Labels for this lane's odd states (8l+1,3,5,7) -> targets[4l..4l+3]
    int e0, e1, e2, e3;
    float sk0, sk1, sk2, sk3;
    {
        const int* tg = targets + n * S_TGT;
        int4 tv = *(const int4*)(tg + 4 * lane);
        e0 = tv.x; e1 = tv.y; e2 = tv.z; e3 = tv.w;
        int prev = (lane == 0) ? -1 : tg[4 * lane - 1];
        sk0 = (lane > 0 && e0 != prev) ? 1.f : 0.f;
        sk1 = (e1 != e0) ? 1.f : 0.f;
        sk2 = (e2 != e1) ? 1.f : 0.f;
        sk3 = (e3 != e2) ? 1.f : 0.f;
    }

    // alpha registers (linear, per-lane frame ls)
    float a0=0.f,a1=0.f,a2=0.f,a3=0.f,a4=0.f,a5=0.f,a6=0.f,a7=0.f,a8=0.f;
    if (lane == 0) { a0 = __expf(lpn[0]); a1 = __expf(lpn[e0]); }
    float ls = 0.f;                        // per-lane log scale
    float f  = (lane == 0) ? 0.f : 1.f;    // e^{ls_{lane-1} - ls_lane}

    // Per-lane renorm + bounded-slack frame reconciliation.
    // Guarantees: post-renorm values <= 1 per lane, f <= e^SLACK, no inf/NaN.
#define RENORM() do {                                                          \
    float m_ = fmaxf(fmaxf(fmaxf(a0,a1), fmaxf(a2,a3)),                        \
                     fmaxf(fmaxf(a4,a5), fmaxf(a6,a7)));                       \
    m_ = fmaxf(m_, a8);                                                        \
    float lsc_ = (m_ > 0.f) ? (ls + __logf(m_)) : -1e37f;                      \
    float t1_ = __shfl_up_sync(FULLM, lsc_, 1);                                \
    if (lane >= 1)  lsc_ = fmaxf(lsc_, t1_ - SLACK);                           \
    float t2_ = __shfl_up_sync(FULLM, lsc_, 2);                                \
    if (lane >= 2)  lsc_ = fmaxf(lsc_, t2_ - 2.f*SLACK);                       \
    float t4_ = __shfl_up_sync(FULLM, lsc_, 4);                                \
    if (lane >= 4)  lsc_ = fmaxf(lsc_, t4_ - 4.f*SLACK);                       \
    float t8_ = __shfl_up_sync(FULLM, lsc_, 8);                                \
    if (lane >= 8)  lsc_ = fmaxf(lsc_, t8_ - 8.f*SLACK);                       \
    float t16_ = __shfl_up_sync(FULLM, lsc_, 16);                              \
    if (lane >= 16) lsc_ = fmaxf(lsc_, t16_ - 16.f*SLACK);                     \
    float sc_ = (m_ > 0.f) ? __expf(0.5f * (ls - lsc_)) : 0.f;                 \
    a0=(a0*sc_)*sc_; a1=(a1*sc_)*sc_; a2=(a2*sc_)*sc_;                         \
    a3=(a3*sc_)*sc_; a4=(a4*sc_)*sc_; a5=(a5*sc_)*sc_;                         \
    a6=(a6*sc_)*sc_; a7=(a7*sc_)*sc_; a8=(a8*sc_)*sc_;                         \
    ls = lsc_;                                                                 \
    float lp_ = __shfl_up_sync(FULLM, ls, 1);                                  \
    f = (lane == 0) ? 0.f : __expf(lp_ - ls);                                  \
} while (0)

    // Register prefetch pipeline: raw log-probs for rows t = 1..PF
    float pb[PF], q0[PF], q1[PF], q2[PF], q3[PF];
    #pragma unroll
    for (int d = 0; d < PF; ++d) {
        const float* r = lpn + ((size_t)(1 + d) << 15);   // row (1+d) * N*C
        pb[d] = r[0]; q0[d] = r[e0]; q1[d] = r[e1]; q2[d] = r[e2]; q3[d] = r[e3];
    }

    int t = 1;
    while (t < inLen) {
        #pragma unroll
        for (int u = 0; u < PF; ++u) {
            if (u == 8) RENORM();              // renorm period 8 (overflow bound)
            const int tt = t + u;
            if (tt >= inLen) break;            // warp-uniform

            float lb = pb[u], l0 = q0[u], l1 = q1[u], l2 = q2[u], l3 = q3[u];
            int tp = tt + PF; if (tp > T_LEN - 1) tp = T_LEN - 1;
            const float* r = lpn + ((size_t)tp << 15);
            pb[u] = r[0]; q0[u] = r[e0]; q1[u] = r[e1]; q2[u] = r[e2]; q3[u] = r[e3];

            float PB = __expf(lb + LNB);
            float P0 = __expf(l0 + LNB);
            float P1 = __expf(l1 + LNB);
            float P2 = __expf(l2 + LNB);
            float P3 = __expf(l3 + LNB);

            // neighbor's old a7 (state 8l-1), rescaled into our frame; f<=e^12
            float nb = __shfl_up_sync(FULLM, a7, 1) * f;

            float n0 = PB * (a0 + nb);
            float n1 = P0 * fmaf(sk0, nb, a0 + a1);
            float n2 = PB * (a2 + a1);
            float n3 = P1 * fmaf(sk1, a1, a2 + a3);
            float n4 = PB * (a4 + a3);
            float n5 = P2 * fmaf(sk2, a3, a4 + a5);
            float n6 = PB * (a6 + a5);
            float n7 = P3 * fmaf(sk3, a5, a6 + a7);
            float n8 = PB * (a8 + a7);         // state 256 (lane 31)

            a0=n0; a1=n1; a2=n2; a3=n3; a4=n4; a5=n5; a6=n6; a7=n7; a8=n8;
        }
        RENORM();
        t += PF;
    }

    // ---- extraction: back to log space (per-lane frame folds in here) ----
    sh[8*lane+0] = (a0 > 0.f) ? __logf(a0) + ls : NEGV;
    sh[8*lane+1] = (a1 > 0.f) ? __logf(a1) + ls : NEGV;
    sh[8*lane+2] = (a2 > 0.f) ? __logf(a2) + ls : NEGV;
    sh[8*lane+3] = (a3 > 0.f) ? __logf(a3) + ls : NEGV;
    sh[8*lane+4] = (a4 > 0.f) ? __logf(a4) + ls : NEGV;
    sh[8*lane+5] = (a5 > 0.f) ? __logf(a5) + ls : NEGV;
    sh[8*lane+6] = (a6 > 0.f) ? __logf(a6) + ls : NEGV;
    sh[8*lane+7] = (a7 > 0.f) ? __logf(a7) + ls : NEGV;
    if (lane == 31) sh[256] = (a8 > 0.f) ? __logf(a8) + ls : NEGV;
    __syncwarp();

    if (lane == 0) {
        int tl  = target_lengths[n];
        int idx = 2 * tl;
        float la = sh[idx], lb = sh[idx - 1];
        float mm = fmaxf(la, lb);
        float lse = mm + __logf(__expf(la - mm) + __expf(lb - mm));
        // remove per-step boost: updates ran for t = 1 .. inLen-1
        float loss = -(lse - (float)(inLen - 1) * LNB);
        g_partial[n] = loss / (float)tl;
        __threadfence();
    }
    __syncwarp();

    // ---- fused deterministic reduction: last-arriving CTA reduces ----
    if (lane == 0) ticket = atomicAdd(&g_count, 1u);
    __syncwarp();
    if (ticket == NB - 1) {
        __threadfence();
        float s = 0.f;
        #pragma unroll
        for (int i = 0; i < NB / 32; ++i)      // fixed order -> deterministic
            s += __ldcg(&g_partial[lane + 32 * i]);
        #pragma unroll
        for (int o = 16; o > 0; o >>= 1)
            s += __shfl_down_sync(FULLM, s, o);
        if (lane == 0) {
            out[0] = s * (1.f / (float)NB);
            g_count = 0;                       // reset for next graph replay
        }
    }
}

extern "C" void kernel_launch(void* const* d_in, const int* in_sizes, int n_in,
                              void* d_out, int out_size)
{
    const float* log_probs      = (const float*)d_in[0];
    const int*   targets        = (const int*)  d_in[1];
    const int*   input_lengths  = (const int*)  d_in[2];
    const int*   target_lengths = (const int*)  d_in[3];

    ctc_kernel<<<NB, 32>>>(log_probs, targets, input_lengths, target_lengths,
                           (float*)d_out);
}

// round 6
// speedup vs baseline: 4.4126x; 3.2411x over previous
#include <cuda_runtime.h>
#include <cstdint>

// Shapes fixed for this problem
#define T_LEN   1024
#define NB      256
#define C_CLASS 128
#define S_TGT   128
#define NCF     (NB * C_CLASS)     // row stride in floats (32768)
#define NEGV    -1e30f
#define RD      16                 // ring depth (rows in flight)
#define FULLM   0xffffffffu
#define SLACK   12.0f              // bounds cross-lane frame factor f <= e^12
#define LOG2E   1.44269504f

__device__ float        g_partial[NB];
__device__ unsigned int g_count;   // zero-init; reset by the reducing CTA each run

#define CP16(dst32, srcg) \
    asm volatile("cp.async.ca.shared.global [%0], [%1], 16;" :: "r"(dst32), "l"(srcg))
#define CPCOMMIT() asm volatile("cp.async.commit_group;")
#define CPWAIT(N)  asm volatile("cp.async.wait_group %0;" :: "n"(N))

// One warp per batch item. 257 extended states in registers:
// lane holds states 8*lane..8*lane+7; lane 31 also state 256 (a8).
// Linear domain with blank factored out (even updates are pure adds),
// per-lane log-scale ls + bounded-slack frame scan, cp.async row ring.
__global__ void __launch_bounds__(32) ctc_kernel(
    const float* __restrict__ log_probs,      // (T, N, C)
    const int*   __restrict__ targets,        // (N, S)
    const int*   __restrict__ input_lengths,  // (N,)
    const int*   __restrict__ target_lengths, // (N,)
    float*       __restrict__ out)
{
    __shared__ float        ring[RD * C_CLASS];   // 8KB row ring
    __shared__ float        sh[257];
    __shared__ unsigned int ticket;

    const int n    = blockIdx.x;
    const int lane = threadIdx.x;
    const float* lpn = log_probs + (size_t)n * C_CLASS;
    const int inLen  = input_lengths[n];
    const unsigned int ring_b = (unsigned int)__cvta_generic_to_shared(ring);

    // Labels for this lane's odd states (8l+1,3,5,7) -> targets[4l..4l+3]
    int e0, e1, e2, e3;
    float sk0, sk1, sk2, sk3;
    {
        const int* tg = targets + n * S_TGT;
        int4 tv = *(const int4*)(tg + 4 * lane);
        e0 = tv.x; e1 = tv.y; e2 = tv.z; e3 = tv.w;
        int prev = (lane == 0) ? -1 : tg[4 * lane - 1];
        sk0 = (lane > 0 && e0 != prev) ? 1.f : 0.f;
        sk1 = (e1 != e0) ? 1.f : 0.f;
        sk2 = (e2 != e1) ? 1.f : 0.f;
        sk3 = (e3 != e2) ? 1.f : 0.f;
    }

    // alpha registers (linear, blank-factored, per-lane frame ls)
    float a0=0.f,a1=0.f,a2=0.f,a3=0.f,a4=0.f,a5=0.f,a6=0.f,a7=0.f,a8=0.f;
    if (lane == 0) { a0 = __expf(lpn[0]); a1 = __expf(lpn[e0]); }
    float ls  = 0.f;                     // per-lane log scale (renorm factors)
    float lsB = 0.f;                     // warp-uniform sum of blank log-probs
    float f   = (lane == 0) ? 0.f : 1.f; // e^{ls_{lane-1} - ls_lane}

#define RENORM() do {                                                          \
    float m_ = fmaxf(fmaxf(fmaxf(a0,a1), fmaxf(a2,a3)),                        \
                     fmaxf(fmaxf(a4,a5), fmaxf(a6,a7)));                       \
    m_ = fmaxf(m_, a8);                                                        \
    float lsc_ = (m_ > 0.f) ? (ls + __logf(m_)) : -1e37f;                      \
    float t1_ = __shfl_up_sync(FULLM, lsc_, 1);                                \
    if (lane >= 1)  lsc_ = fmaxf(lsc_, t1_ - SLACK);                           \
    float t2_ = __shfl_up_sync(FULLM, lsc_, 2);                                \
    if (lane >= 2)  lsc_ = fmaxf(lsc_, t2_ - 2.f*SLACK);                       \
    float t4_ = __shfl_up_sync(FULLM, lsc_, 4);                                \
    if (lane >= 4)  lsc_ = fmaxf(lsc_, t4_ - 4.f*SLACK);                       \
    float t8_ = __shfl_up_sync(FULLM, lsc_, 8);                                \
    if (lane >= 8)  lsc_ = fmaxf(lsc_, t8_ - 8.f*SLACK);                       \
    float t16_ = __shfl_up_sync(FULLM, lsc_, 16);                              \
    if (lane >= 16) lsc_ = fmaxf(lsc_, t16_ - 16.f*SLACK);                     \
    float sc_ = (m_ > 0.f) ? __expf(0.5f * (ls - lsc_)) : 0.f;                 \
    a0=(a0*sc_)*sc_; a1=(a1*sc_)*sc_; a2=(a2*sc_)*sc_;                         \
    a3=(a3*sc_)*sc_; a4=(a4*sc_)*sc_; a5=(a5*sc_)*sc_;                         \
    a6=(a6*sc_)*sc_; a7=(a7*sc_)*sc_; a8=(a8*sc_)*sc_;                         \
    ls = lsc_;                                                                 \
    float lp_ = __shfl_up_sync(FULLM, ls, 1);                                  \
    f = (lane == 0) ? 0.f : __expf(lp_ - ls);                                  \
} while (0)

    // ---- prologue: fill ring with rows 1..RD (one commit group per row) ----
    #pragma unroll
    for (int d = 0; d < RD; ++d) {
        const float* src = lpn + (size_t)(1 + d) * NCF + lane * 4;
        unsigned int dst = ring_b + (unsigned int)((d * C_CLASS + lane * 4) * 4);
        CP16(dst, src); CPCOMMIT();
    }
    // stage row 1 (slot 0): blank lp + label ratios
    float lb, r0, r1, r2, r3;
    {
        CPWAIT(RD - 1);                         // row 1 arrived
        const float* rw = ring;                 // slot 0
        lb = rw[0];
        float v0 = rw[e0], v1 = rw[e1], v2 = rw[e2], v3 = rw[e3];
        r0 = exp2f((v0 - lb) * LOG2E);
        r1 = exp2f((v1 - lb) * LOG2E);
        r2 = exp2f((v2 - lb) * LOG2E);
        r3 = exp2f((v3 - lb) * LOG2E);
    }

    int t = 1;
    while (t < inLen) {
        #pragma unroll
        for (int u = 0; u < 8; ++u) {
            const int tt = t + u;
            if (tt >= inLen) break;            // warp-uniform

            // prefetch row tt+RD into slot(tt) = (tt-1)%RD (consumed last iter)
            int rowpf = tt + RD; if (rowpf > T_LEN - 1) rowpf = T_LEN - 1;
            {
                const float* src = lpn + (size_t)rowpf * NCF + lane * 4;
                unsigned int dst = ring_b +
                    (unsigned int)(((((tt - 1) & (RD - 1)) * C_CLASS) + lane * 4) * 4);
                CP16(dst, src); CPCOMMIT();
            }
            CPWAIT(RD - 1);                    // row tt+1 arrived

            // stage row tt+1 from slot tt%RD (unused garbage if tt+1 == inLen)
            const float* rw = ring + (tt & (RD - 1)) * C_CLASS;
            float lbn = rw[0];
            float w0 = rw[e0], w1 = rw[e1], w2 = rw[e2], w3 = rw[e3];
            float s0 = exp2f((w0 - lbn) * LOG2E);
            float s1 = exp2f((w1 - lbn) * LOG2E);
            float s2 = exp2f((w2 - lbn) * LOG2E);
            float s3 = exp2f((w3 - lbn) * LOG2E);

            // recurrence for step tt (blank factored out: evens are pure adds)
            lsB += lb;
            float nb = __shfl_up_sync(FULLM, a7, 1) * f;   // state 8l-1, rescaled

            float n0 = a0 + nb;
            float n1 = r0 * fmaf(sk0, nb, a0 + a1);
            float n2 = a2 + a1;
            float n3 = r1 * fmaf(sk1, a1, a2 + a3);
            float n4 = a4 + a3;
            float n5 = r2 * fmaf(sk2, a3, a4 + a5);
            float n6 = a6 + a5;
            float n7 = r3 * fmaf(sk3, a5, a6 + a7);
            float n8 = a8 + a7;                // state 256 (lane 31)

            a0=n0; a1=n1; a2=n2; a3=n3; a4=n4; a5=n5; a6=n6; a7=n7; a8=n8;
            lb = lbn; r0 = s0; r1 = s1; r2 = s2; r3 = s3;
        }
        RENORM();
        t += 8;
    }
    CPWAIT(0);                                  // drain async copies

    // ---- extraction: log alpha = log b + ls + lsB ----
    sh[8*lane+0] = (a0 > 0.f) ? __logf(a0) + ls + lsB : NEGV;
    sh[8*lane+1] = (a1 > 0.f) ? __logf(a1) + ls + lsB : NEGV;
    sh[8*lane+2] = (a2 > 0.f) ? __logf(a2) + ls + lsB : NEGV;
    sh[8*lane+3] = (a3 > 0.f) ? __logf(a3) + ls + lsB : NEGV;
    sh[8*lane+4] = (a4 > 0.f) ? __logf(a4) + ls + lsB : NEGV;
    sh[8*lane+5] = (a5 > 0.f) ? __logf(a5) + ls + lsB : NEGV;
    sh[8*lane+6] = (a6 > 0.f) ? __logf(a6) + ls + lsB : NEGV;
    sh[8*lane+7] = (a7 > 0.f) ? __logf(a7) + ls + lsB : NEGV;
    if (lane == 31) sh[256] = (a8 > 0.f) ? __logf(a8) + ls + lsB : NEGV;
    __syncwarp();

    if (lane == 0) {
        int tl  = target_lengths[n];
        int idx = 2 * tl;
        float la = sh[idx], lb2 = sh[idx - 1];
        float mm = fmaxf(la, lb2);
        float lse = mm + __logf(__expf(la - mm) + __expf(lb2 - mm));
        g_partial[n] = -lse / (float)tl;
        __threadfence();
    }
    __syncwarp();

    // ---- fused deterministic reduction: last-arriving CTA reduces ----
    if (lane == 0) ticket = atomicAdd(&g_count, 1u);
    __syncwarp();
    if (ticket == NB - 1) {
        __threadfence();
        float s = 0.f;
        #pragma unroll
        for (int i = 0; i < NB / 32; ++i)      // fixed order -> deterministic
            s += __ldcg(&g_partial[lane + 32 * i]);
        #pragma unroll
        for (int o = 16; o > 0; o >>= 1)
            s += __shfl_down_sync(FULLM, s, o);
        if (lane == 0) {
            out[0] = s * (1.f / (float)NB);
            g_count = 0;                       // reset for next graph replay
        }
    }
}

extern "C" void kernel_launch(void* const* d_in, const int* in_sizes, int n_in,
                              void* d_out, int out_size)
{
    const float* log_probs      = (const float*)d_in[0];
    const int*   targets        = (const int*)  d_in[1];
    const int*   input_lengths  = (const int*)  d_in[2];
    const int*   target_lengths = (const int*)  d_in[3];

    ctc_kernel<<<NB, 32>>>(log_probs, targets, input_lengths, target_lengths,
                           (float*)d_out);
}

// round 7
// speedup vs baseline: 4.5128x; 1.0227x over previous
#include <cuda_runtime.h>
#include <cstdint>

// Shapes fixed for this problem
#define T_LEN   1024
#define NB      256
#define C_CLASS 128
#define S_TGT   128
#define NCF     (NB * C_CLASS)     // row stride in floats (32768)
#define NEGV    -1e30f
#define RD      16                 // ring depth (rows in flight)
#define FULLM   0xffffffffu
#define SLACK   12.0f              // bounds cross-lane frame factor f <= e^12

__device__ float        g_partial[NB];
__device__ unsigned int g_count;   // zero-init; reset by the reducing CTA each run

#define CP16(dst32, srcg) \
    asm volatile("cp.async.ca.shared.global [%0], [%1], 16;" :: "r"(dst32), "l"(srcg))
#define CPCOMMIT() asm volatile("cp.async.commit_group;")
#define CPWAIT(N)  asm volatile("cp.async.wait_group %0;" :: "n"(N))

// One warp per batch item. 257 extended states in registers:
// lane holds states 8*lane..8*lane+7; lane 31 also state 256 (a8).
// Linear domain, blank factored out (even-state updates are pure adds),
// per-lane log-scale ls + bounded-slack frame scan, cp.async row ring.
__global__ void __launch_bounds__(32) ctc_kernel(
    const float* __restrict__ log_probs,      // (T, N, C)
    const int*   __restrict__ targets,        // (N, S)
    const int*   __restrict__ input_lengths,  // (N,)
    const int*   __restrict__ target_lengths, // (N,)
    float*       __restrict__ out)
{
    __shared__ float        ring[RD * C_CLASS];   // 8KB row ring
    __shared__ float        sh[257];
    __shared__ unsigned int ticket;

    const int n    = blockIdx.x;
    const int lane = threadIdx.x;
    const float* lpn = log_probs + (size_t)n * C_CLASS;
    const int inLen  = input_lengths[n];
    const unsigned int ring_b = (unsigned int)__cvta_generic_to_shared(ring);

    // Labels for this lane's odd states (8l+1,3,5,7) -> targets[4l..4l+3]
    int e0, e1, e2, e3;
    float sk0, sk1, sk2, sk3;
    {
        const int* tg = targets + n * S_TGT;
        int4 tv = *(const int4*)(tg + 4 * lane);
        e0 = tv.x; e1 = tv.y; e2 = tv.z; e3 = tv.w;
        int prev = (lane == 0) ? -1 : tg[4 * lane - 1];
        sk0 = (lane > 0 && e0 != prev) ? 1.f : 0.f;
        sk1 = (e1 != e0) ? 1.f : 0.f;
        sk2 = (e2 != e1) ? 1.f : 0.f;
        sk3 = (e3 != e2) ? 1.f : 0.f;
    }

    // alpha registers (linear, blank-factored, per-lane frame ls)
    float a0=0.f,a1=0.f,a2=0.f,a3=0.f,a4=0.f,a5=0.f,a6=0.f,a7=0.f,a8=0.f;
    if (lane == 0) { a0 = __expf(lpn[0]); a1 = __expf(lpn[e0]); }
    float ls  = 0.f;                     // per-lane log scale (renorm factors)
    float lsB = 0.f;                     // warp-uniform sum of blank log-probs
    float f   = (lane == 0) ? 0.f : 1.f; // e^{ls_{lane-1} - ls_lane}

#define RENORM() do {                                                          \
    float m_ = fmaxf(fmaxf(fmaxf(a0,a1), fmaxf(a2,a3)),                        \
                     fmaxf(fmaxf(a4,a5), fmaxf(a6,a7)));                       \
    m_ = fmaxf(m_, a8);                                                        \
    float lsc_ = (m_ > 0.f) ? (ls + __logf(m_)) : -1e37f;                      \
    float t1_ = __shfl_up_sync(FULLM, lsc_, 1);                                \
    if (lane >= 1)  lsc_ = fmaxf(lsc_, t1_ - SLACK);                           \
    float t2_ = __shfl_up_sync(FULLM, lsc_, 2);                                \
    if (lane >= 2)  lsc_ = fmaxf(lsc_, t2_ - 2.f*SLACK);                       \
    float t4_ = __shfl_up_sync(FULLM, lsc_, 4);                                \
    if (lane >= 4)  lsc_ = fmaxf(lsc_, t4_ - 4.f*SLACK);                       \
    float t8_ = __shfl_up_sync(FULLM, lsc_, 8);                                \
    if (lane >= 8)  lsc_ = fmaxf(lsc_, t8_ - 8.f*SLACK);                       \
    float t16_ = __shfl_up_sync(FULLM, lsc_, 16);                              \
    if (lane >= 16) lsc_ = fmaxf(lsc_, t16_ - 16.f*SLACK);                     \
    float sc_ = (m_ > 0.f) ? __expf(0.5f * (ls - lsc_)) : 0.f;                 \
    a0=(a0*sc_)*sc_; a1=(a1*sc_)*sc_; a2=(a2*sc_)*sc_;                         \
    a3=(a3*sc_)*sc_; a4=(a4*sc_)*sc_; a5=(a5*sc_)*sc_;                         \
    a6=(a6*sc_)*sc_; a7=(a7*sc_)*sc_; a8=(a8*sc_)*sc_;                         \
    ls = lsc_;                                                                 \
    float lp_ = __shfl_up_sync(FULLM, ls, 1);                                  \
    f = (lane == 0) ? 0.f : __expf(lp_ - ls);                                  \
} while (0)

    // ---- prologue: fill ring with rows 1..RD (one commit group per row) ----
    const float* src_pf = lpn + (size_t)1 * NCF + lane * 4;   // running src ptr
    #pragma unroll
    for (int d = 0; d < RD; ++d) {
        unsigned int dst = ring_b + (unsigned int)((d * C_CLASS + lane * 4) * 4);
        CP16(dst, src_pf); CPCOMMIT();
        src_pf += NCF;
    }
    // stage row 1 (slot 0): blank lp + label ratios (MUFU intrinsics only)
    float lb, r0, r1, r2, r3;
    {
        CPWAIT(RD - 1);                         // row 1 arrived
        const float* rw = ring;                 // slot 0
        lb = rw[0];
        r0 = __expf(rw[e0] - lb);
        r1 = __expf(rw[e1] - lb);
        r2 = __expf(rw[e2] - lb);
        r3 = __expf(rw[e3] - lb);
    }

    const float* src_end = lpn + (size_t)(T_LEN - 1) * NCF + lane * 4;
    int t = 1;
    while (t < inLen) {
        #pragma unroll
        for (int u = 0; u < 8; ++u) {
            const int tt = t + u;
            if (tt >= inLen) break;            // warp-uniform

            // prefetch row tt+RD into slot (tt-1)%RD (consumed last iter)
            {
                const float* src = (src_pf <= src_end) ? src_pf : src_end;
                unsigned int dst = ring_b +
                    (unsigned int)(((((tt - 1) & (RD - 1)) * C_CLASS) + lane * 4) * 4);
                CP16(dst, src); CPCOMMIT();
                src_pf += NCF;
            }
            CPWAIT(RD - 1);                    // row tt+1 arrived

            // stage row tt+1 from slot tt%RD (garbage unused if tt+1 == inLen)
            const float* rw = ring + (tt & (RD - 1)) * C_CLASS;
            float lbn = rw[0];
            float s0 = __expf(rw[e0] - lbn);
            float s1 = __expf(rw[e1] - lbn);
            float s2 = __expf(rw[e2] - lbn);
            float s3 = __expf(rw[e3] - lbn);

            // recurrence for step tt (blank factored: evens are pure adds)
            lsB += lb;
            float nb = __shfl_up_sync(FULLM, a7, 1) * f;   // state 8l-1, rescaled

            float n0 = a0 + nb;
            float n1 = r0 * fmaf(sk0, nb, a0 + a1);
            float n2 = a2 + a1;
            float n3 = r1 * fmaf(sk1, a1, a2 + a3);
            float n4 = a4 + a3;
            float n5 = r2 * fmaf(sk2, a3, a4 + a5);
            float n6 = a6 + a5;
            float n7 = r3 * fmaf(sk3, a5, a6 + a7);
            float n8 = a8 + a7;                // state 256 (lane 31)

            a0=n0; a1=n1; a2=n2; a3=n3; a4=n4; a5=n5; a6=n6; a7=n7; a8=n8;
            lb = lbn; r0 = s0; r1 = s1; r2 = s2; r3 = s3;
        }
        RENORM();
        t += 8;
    }
    CPWAIT(0);                                  // drain async copies

    // ---- extraction: log alpha = log a + ls + lsB ----
    sh[8*lane+0] = (a0 > 0.f) ? __logf(a0) + ls + lsB : NEGV;
    sh[8*lane+1] = (a1 > 0.f) ? __logf(a1) + ls + lsB : NEGV;
    sh[8*lane+2] = (a2 > 0.f) ? __logf(a2) + ls + lsB : NEGV;
    sh[8*lane+3] = (a3 > 0.f) ? __logf(a3) + ls + lsB : NEGV;
    sh[8*lane+4] = (a4 > 0.f) ? __logf(a4) + ls + lsB : NEGV;
    sh[8*lane+5] = (a5 > 0.f) ? __logf(a5) + ls + lsB : NEGV;
    sh[8*lane+6] = (a6 > 0.f) ? __logf(a6) + ls + lsB : NEGV;
    sh[8*lane+7] = (a7 > 0.f) ? __logf(a7) + ls + lsB : NEGV;
    if (lane == 31) sh[256] = (a8 > 0.f) ? __logf(a8) + ls + lsB : NEGV;
    __syncwarp();

    if (lane == 0) {
        int tl  = target_lengths[n];
        int idx = 2 * tl;
        float la = sh[idx], lb2 = sh[idx - 1];
        float mm = fmaxf(la, lb2);
        float lse = mm + __logf(__expf(la - mm) + __expf(lb2 - mm));
        g_partial[n] = -lse / (float)tl;
        __threadfence();
    }
    __syncwarp();

    // ---- fused deterministic reduction: last-arriving CTA reduces ----
    if (lane == 0) ticket = atomicAdd(&g_count, 1u);
    __syncwarp();
    if (ticket == NB - 1) {
        __threadfence();
        float s = 0.f;
        #pragma unroll
        for (int i = 0; i < NB / 32; ++i)      // fixed order -> deterministic
            s += __ldcg(&g_partial[lane + 32 * i]);
        #pragma unroll
        for (int o = 16; o > 0; o >>= 1)
            s += __shfl_down_sync(FULLM, s, o);
        if (lane == 0) {
            out[0] = s * (1.f / (float)NB);
            g_count = 0;                       // reset for next graph replay
        }
    }
}

extern "C" void kernel_launch(void* const* d_in, const int* in_sizes, int n_in,
                              void* d_out, int out_size)
{
    const float* log_probs      = (const float*)d_in[0];
    const int*   targets        = (const int*)  d_in[1];
    const int*   input_lengths  = (const int*)  d_in[2];
    const int*   target_lengths = (const int*)  d_in[3];

    ctc_kernel<<<NB, 32>>>(log_probs, targets, input_lengths, target_lengths,
                           (float*)d_out);
}

// round 8
// speedup vs baseline: 6.4083x; 1.4200x over previous
#include <cuda_runtime.h>
#include <cstdint>

// Shapes fixed for this problem
#define T_LEN   1024
#define NB      256
#define C_CLASS 128
#define S_TGT   128
#define NCF     (NB * C_CLASS)
#define ROWB    (NCF * 4)            // bytes per time-row (131072)
#define NEGV    -1e30f
#define FULLM   0xffffffffu
#define SLACK   12.0f                // bounds cross-lane frame factor f <= e^12
#define WPB     2                    // warps (batch items) per CTA
#define HALF    (8 * C_CLASS)        // floats per ring half (one 8-row block)

__device__ float        g_partial[NB];
__device__ unsigned int g_count;     // zero-init; reset by the reducing warp

#define CP16(dst32, srcg) \
    asm volatile("cp.async.ca.shared.global [%0], [%1], 16;" :: "r"(dst32), "l"(srcg))
#define CPCOMMIT() asm volatile("cp.async.commit_group;")
#define CPWAIT(N)  asm volatile("cp.async.wait_group %0;" :: "n"(N))

// One warp per batch item, two warps per CTA (distinct SMSPs). 257 states in
// registers: lane holds 8*lane..8*lane+7; lane 31 also state 256 (a8).
// Linear domain, blank factored out; per-lane log-scale + bounded-slack scan;
// block-level cp.async 3-half ring (one commit group per 8 rows).
__global__ void __launch_bounds__(32 * WPB) ctc_kernel(
    const float* __restrict__ log_probs,      // (T, N, C)
    const int*   __restrict__ targets,        // (N, S)
    const int*   __restrict__ input_lengths,  // (N,)
    const int*   __restrict__ target_lengths, // (N,)
    float*       __restrict__ out)
{
    __shared__ float ring[WPB][3 * HALF];     // 12 KB per warp
    __shared__ float sh[WPB][257];

    const int wid  = threadIdx.x >> 5;
    const int lane = threadIdx.x & 31;
    const int n    = blockIdx.x * WPB + wid;
    const float* lpn = log_probs + (size_t)n * C_CLASS;
    const char*  srcb = (const char*)lpn + lane * 16;   // +row*ROWB per row
    const int inLen = input_lengths[n];

    float* myring = &ring[wid][0];
    const unsigned ring_s = (unsigned)__cvta_generic_to_shared(myring);

    // Labels for this lane's odd states (8l+1,3,5,7) -> targets[4l..4l+3]
    int e0, e1, e2, e3;
    float sk0, sk1, sk2, sk3;
    {
        const int* tg = targets + n * S_TGT;
        int4 tv = *(const int4*)(tg + 4 * lane);
        e0 = tv.x; e1 = tv.y; e2 = tv.z; e3 = tv.w;
        int prev = (lane == 0) ? -1 : tg[4 * lane - 1];
        sk0 = (lane > 0 && e0 != prev) ? 1.f : 0.f;
        sk1 = (e1 != e0) ? 1.f : 0.f;
        sk2 = (e2 != e1) ? 1.f : 0.f;
        sk3 = (e3 != e2) ? 1.f : 0.f;
    }

    // alpha registers (linear, blank-factored, per-lane frame ls)
    float a0=0.f,a1=0.f,a2=0.f,a3=0.f,a4=0.f,a5=0.f,a6=0.f,a7=0.f,a8=0.f;
    if (lane == 0) { a0 = __expf(lpn[0]); a1 = __expf(lpn[e0]); }
    float ls  = 0.f;                     // per-lane log scale
    float lsB = 0.f;                     // warp-uniform sum of blank log-probs
    float f   = (lane == 0) ? 0.f : 1.f; // e^{ls_{lane-1} - ls_lane}

#define RENORM() do {                                                          \
    float m_ = fmaxf(fmaxf(fmaxf(a0,a1), fmaxf(a2,a3)),                        \
                     fmaxf(fmaxf(a4,a5), fmaxf(a6,a7)));                       \
    m_ = fmaxf(m_, a8);                                                        \
    float lsc_ = (m_ > 0.f) ? (ls + __logf(m_)) : -1e37f;                      \
    float t1_ = __shfl_up_sync(FULLM, lsc_, 1);                                \
    if (lane >= 1)  lsc_ = fmaxf(lsc_, t1_ - SLACK);                           \
    float t2_ = __shfl_up_sync(FULLM, lsc_, 2);                                \
    if (lane >= 2)  lsc_ = fmaxf(lsc_, t2_ - 2.f*SLACK);                       \
    float t4_ = __shfl_up_sync(FULLM, lsc_, 4);                                \
    if (lane >= 4)  lsc_ = fmaxf(lsc_, t4_ - 4.f*SLACK);                       \
    float t8_ = __shfl_up_sync(FULLM, lsc_, 8);                                \
    if (lane >= 8)  lsc_ = fmaxf(lsc_, t8_ - 8.f*SLACK);                       \
    float t16_ = __shfl_up_sync(FULLM, lsc_, 16);                              \
    if (lane >= 16) lsc_ = fmaxf(lsc_, t16_ - 16.f*SLACK);                     \
    float sc_ = (m_ > 0.f) ? __expf(0.5f * (ls - lsc_)) : 0.f;                 \
    a0=(a0*sc_)*sc_; a1=(a1*sc_)*sc_; a2=(a2*sc_)*sc_;                         \
    a3=(a3*sc_)*sc_; a4=(a4*sc_)*sc_; a5=(a5*sc_)*sc_;                         \
    a6=(a6*sc_)*sc_; a7=(a7*sc_)*sc_; a8=(a8*sc_)*sc_;                         \
    ls = lsc_;                                                                 \
    float lp_ = __shfl_up_sync(FULLM, ls, 1);                                  \
    f = (lane == 0) ? 0.f : __expf(lp_ - ls);                                  \
} while (0)

#define STEP_BODY()                                                            \
    float s0 = __expf(w0 - lbn);                                               \
    float s1 = __expf(w1 - lbn);                                               \
    float s2 = __expf(w2 - lbn);                                               \
    float s3 = __expf(w3 - lbn);                                               \
    lsB += lb;                                                                 \
    float nbv = __shfl_up_sync(FULLM, a7, 1) * f;                              \
    float n0 = a0 + nbv;                                                       \
    float n1 = r0 * fmaf(sk0, nbv, a0 + a1);                                   \
    float n2 = a2 + a1;                                                        \
    float n3 = r1 * fmaf(sk1, a1, a2 + a3);                                    \
    float n4 = a4 + a3;                                                        \
    float n5 = r2 * fmaf(sk2, a3, a4 + a5);                                    \
    float n6 = a6 + a5;                                                        \
    float n7 = r3 * fmaf(sk3, a5, a6 + a7);                                    \
    float n8 = a8 + a7;                                                        \
    a0=n0; a1=n1; a2=n2; a3=n3; a4=n4; a5=n5; a6=n6; a7=n7; a8=n8;             \
    lb = lbn; r0 = s0; r1 = s1; r2 = s2; r3 = s3

    // ---- prologue: issue blocks 0,1,2 (rows 1..8, 9..16, 17..24) ----
    #pragma unroll
    for (int k = 0; k < 3; ++k) {
        unsigned d = ring_s + (unsigned)(k * (HALF * 4)) + lane * 16;
        const char* s = srcb + (size_t)(1 + 8 * k) * ROWB;
        #pragma unroll
        for (int j = 0; j < 8; ++j)
            CP16(d + j * 512, s + (size_t)j * ROWB);
        CPCOMMIT();
    }
    CPWAIT(1);                               // blocks 0,1 ready

    // stage row 1 (half0 slot0)
    float lb, r0, r1, r2, r3;
    lb = myring[0];
    r0 = __expf(myring[e0] - lb);
    r1 = __expf(myring[e1] - lb);
    r2 = __expf(myring[e2] - lb);
    r3 = __expf(myring[e3] - lb);

    int t = 1;
    int h = 0;                               // half holding block for t
    while (t + 8 <= inLen) {
        const int nh2 = (h == 2) ? 0 : h + 1;
        const float* ph = myring + h * HALF;
        const float* pn = myring + nh2 * HALF;
        const float* pB = ph;
        const float* p0 = ph + e0;  const float* p1 = ph + e1;
        const float* p2 = ph + e2;  const float* p3 = ph + e3;
        const float pnB = pn[0];
        // (next-half slot0 gathers, loaded up-front: block k+1 is ready)
        const float pn0 = pn[e0], pn1 = pn[e1], pn2 = pn[e2], pn3 = pn[e3];

        #pragma unroll
        for (int u = 0; u < 8; ++u) {
            float lbn, w0, w1, w2, w3;
            if (u < 7) {
                const int o = (u + 1) * C_CLASS;
                lbn = pB[o]; w0 = p0[o]; w1 = p1[o]; w2 = p2[o]; w3 = p3[o];
            } else {
                lbn = pnB; w0 = pn0; w1 = pn1; w2 = pn2; w3 = pn3;
            }
            STEP_BODY();
        }

        // prefetch rows t+24..t+31 into half h (just consumed)
        {
            unsigned d = ring_s + (unsigned)(h * (HALF * 4)) + lane * 16;
            const int rs = t + 24;
            if (rs + 7 <= T_LEN - 1) {
                const char* s = srcb + (size_t)rs * ROWB;
                #pragma unroll
                for (int j = 0; j < 8; ++j)
                    CP16(d + j * 512, s + (size_t)j * ROWB);
            } else {
                #pragma unroll
                for (int j = 0; j < 8; ++j) {
                    int r = rs + j; if (r > T_LEN - 1) r = T_LEN - 1;
                    CP16(d + j * 512, srcb + (size_t)r * ROWB);
                }
            }
            CPCOMMIT();
        }
        RENORM();
        t += 8;
        h = nh2;
        CPWAIT(1);                           // next block ready, one in flight
    }

    // ---- remainder: steps t..inLen-1 (cold, <= 7 iterations) ----
    for (int tt = t; tt < inLen; ++tt) {
        int r = tt + 1; if (r > T_LEN - 1) r = T_LEN - 1;
        const int b = (r - 1) >> 3;
        const float* q = myring + (b % 3) * HALF + ((r - 1) & 7) * C_CLASS;
        float lbn = q[0];
        float w0 = q[e0], w1 = q[e1], w2 = q[e2], w3 = q[e3];
        STEP_BODY();
    }
    CPWAIT(0);                               // drain async copies

    // ---- extraction: log alpha = log a + ls + lsB ----
    float* shw = &sh[wid][0];
    shw[8*lane+0] = (a0 > 0.f) ? __logf(a0) + ls + lsB : NEGV;
    shw[8*lane+1] = (a1 > 0.f) ? __logf(a1) + ls + lsB : NEGV;
    shw[8*lane+2] = (a2 > 0.f) ? __logf(a2) + ls + lsB : NEGV;
    shw[8*lane+3] = (a3 > 0.f) ? __logf(a3) + ls + lsB : NEGV;
    shw[8*lane+4] = (a4 > 0.f) ? __logf(a4) + ls + lsB : NEGV;
    shw[8*lane+5] = (a5 > 0.f) ? __logf(a5) + ls + lsB : NEGV;
    shw[8*lane+6] = (a6 > 0.f) ? __logf(a6) + ls + lsB : NEGV;
    shw[8*lane+7] = (a7 > 0.f) ? __logf(a7) + ls + lsB : NEGV;
    if (lane == 31) shw[256] = (a8 > 0.f) ? __logf(a8) + ls + lsB : NEGV;
    __syncwarp();

    if (lane == 0) {
        int tl  = target_lengths[n];
        int idx = 2 * tl;
        float la = shw[idx], lb2 = shw[idx - 1];
        float mm = fmaxf(la, lb2);
        float lse = mm + __logf(__expf(la - mm) + __expf(lb2 - mm));
        g_partial[n] = -lse / (float)tl;
        __threadfence();
    }
    __syncwarp();

    // ---- fused deterministic reduction: last-arriving warp reduces ----
    unsigned tk = 0;
    if (lane == 0) tk = atomicAdd(&g_count, 1u);
    tk = __shfl_sync(FULLM, tk, 0);
    if (tk == NB - 1) {
        __threadfence();
        float s = 0.f;
        #pragma unroll
        for (int i = 0; i < NB / 32; ++i)    // fixed order -> deterministic
            s += __ldcg(&g_partial[lane + 32 * i]);
        #pragma unroll
        for (int o = 16; o > 0; o >>= 1)
            s += __shfl_down_sync(FULLM, s, o);
        if (lane == 0) {
            out[0] = s * (1.f / (float)NB);
            g_count = 0;                     // reset for next graph replay
        }
    }
}

extern "C" void kernel_launch(void* const* d_in, const int* in_sizes, int n_in,
                              void* d_out, int out_size)
{
    const float* log_probs      = (const float*)d_in[0];
    const int*   targets        = (const int*)  d_in[1];
    const int*   input_lengths  = (const int*)  d_in[2];
    const int*   target_lengths = (const int*)  d_in[3];

    ctc_kernel<<<NB / WPB, 32 * WPB>>>(log_probs, targets, input_lengths,
                                       target_lengths, (float*)d_out);
}

// round 9
// speedup vs baseline: 7.0197x; 1.0954x over previous
#include <cuda_runtime.h>
#include <cstdint>

// Shapes fixed for this problem
#define T_LEN   1024
#define NB      256
#define C_CLASS 128
#define S_TGT   128
#define NCF     (NB * C_CLASS)
#define ROWB    (NCF * 4)
#define NEGV    -1e30f
#define FULLM   0xffffffffu
#define SLACK   12.0f
#define NH      5                  // ring halves per pair (HI lags LO by 1 block)
#define HALF    (8 * C_CLASS)      // floats per half (8 rows)

__device__ float        g_partial[NB];
__device__ unsigned int g_count;

#define CP16(d,s)  asm volatile("cp.async.ca.shared.global [%0], [%1], 16;" :: "r"(d), "l"(s))
#define CPCOMMIT() asm volatile("cp.async.commit_group;")
#define CPWAIT(N)  asm volatile("cp.async.wait_group %0;" :: "n"(N))
#define BARP(id)   asm volatile("bar.sync %0, 64;" :: "r"(id) : "memory")

struct __align__(16) PairShared {
    float ring[NH * HALF];   // 20 KB: log-prob rows, shared by LO/HI warps
    float bnd[4][8];         // per-block boundary values a[127] (pre-update)
    float lsb[4];            // LO lane31 frame per block
    float sh[257];           // final log-alphas
};

// One warp handles half the extended-state chain for one batch item.
// LO: states 0..127 (4/lane). HI: states 128..256 (4/lane + state 256 on lane31).
// HI lags LO by one 8-step block; LO publishes boundary a[127] per step + frame.
template<bool HI>
__device__ __forceinline__ void ctc_warp(
    PairShared* ps, const float* lpn, const int* tg,
    int inLen, int lane, int barid)
{
    const int base = HI ? 64 : 0;
    int2 ev = *(const int2*)(tg + base + 2 * lane);
    const int e0 = ev.x, e1 = ev.y;
    const int prevl = (HI || lane > 0) ? tg[base + 2 * lane - 1] : 0;
    const float sk0 = (!HI && lane == 0) ? 0.f : ((e0 != prevl) ? 1.f : 0.f);
    const float sk1 = (e1 != e0) ? 1.f : 0.f;

    float a0=0.f, a1=0.f, a2=0.f, a3=0.f, a4=0.f;
    if (!HI && lane == 0) { a0 = __expf(lpn[0]); a1 = __expf(lpn[e0]); }
    float ls = 0.f, lsB = 0.f;
    float f  = (!HI && lane == 0) ? 0.f : 1.f;

    const char* srcb = (const char*)lpn + lane * 16;
    const unsigned ring_s = (unsigned)__cvta_generic_to_shared(ps->ring);

    const int K = (inLen - 1) >> 3;      // full 8-step blocks
    const int R = (inLen - 1) & 7;       // remainder steps

    float lb = 0.f, r0 = 0.f, r1 = 0.f;  // staged current row (blank lp + ratios)

    // ---- per-lane renorm + bounded-slack frame scan (validated R4 scheme) ----
    auto renorm = [&](float clampls) {
        float m = fmaxf(fmaxf(a0, a1), fmaxf(a2, a3));
        if (HI) m = fmaxf(m, a4);
        float lsc = (m > 0.f) ? (ls + __logf(m)) : -1e37f;
        if (HI && lane == 0) lsc = fmaxf(lsc, clampls - SLACK);  // BEFORE scan
        float t1 = __shfl_up_sync(FULLM, lsc, 1);
        if (lane >= 1)  lsc = fmaxf(lsc, t1 - SLACK);
        float t2 = __shfl_up_sync(FULLM, lsc, 2);
        if (lane >= 2)  lsc = fmaxf(lsc, t2 - 2.f * SLACK);
        float t4 = __shfl_up_sync(FULLM, lsc, 4);
        if (lane >= 4)  lsc = fmaxf(lsc, t4 - 4.f * SLACK);
        float t8 = __shfl_up_sync(FULLM, lsc, 8);
        if (lane >= 8)  lsc = fmaxf(lsc, t8 - 8.f * SLACK);
        float t16 = __shfl_up_sync(FULLM, lsc, 16);
        if (lane >= 16) lsc = fmaxf(lsc, t16 - 16.f * SLACK);
        float sc = (m > 0.f) ? __expf(0.5f * (ls - lsc)) : 0.f;
        a0 = (a0 * sc) * sc; a1 = (a1 * sc) * sc;
        a2 = (a2 * sc) * sc; a3 = (a3 * sc) * sc;
        if (HI) a4 = (a4 * sc) * sc;
        ls = lsc;
        float lp = __shfl_up_sync(FULLM, ls, 1);
        f = __expf(lp - ls);
        if (!HI && lane == 0) f = 0.f;
    };

    // ---- one 8-step block (block j, rows in half hj; stages one row ahead) ----
    auto block8 = [&](int j, int hj) {
        const float* ph = ps->ring + hj * HALF;
        int hn = hj + 1; if (hn == NH) hn = 0;
        const float* pn = ps->ring + hn * HALF;
        float fw = 0.f;
        const float* bb = ps->bnd[j & 3];
        float*       bw = ps->bnd[j & 3];
        if (HI) fw = __expf(ps->lsb[j & 3] - ls);
        #pragma unroll
        for (int u = 0; u < 8; ++u) {
            float lbn, w0, w1;
            if (u < 7) {
                const int o = (u + 1) * C_CLASS;
                lbn = ph[o]; w0 = ph[o + e0]; w1 = ph[o + e1];
            } else {
                lbn = pn[0]; w0 = pn[e0]; w1 = pn[e1];
            }
            float s0 = __expf(w0 - lbn);
            float s1 = __expf(w1 - lbn);
            if (!HI) { if (lane == 31) bw[u] = a3; }   // pre-update a[127]
            float shv = __shfl_up_sync(FULLM, a3, 1);
            float nbv = shv * f;
            if (HI) { if (lane == 0) nbv = bb[u] * fw; }
            lsB += lb;
            float n0 = a0 + nbv;
            float n1 = r0 * fmaf(sk0, nbv, a0 + a1);
            float n2 = a2 + a1;
            float n3 = r1 * fmaf(sk1, a1, a2 + a3);
            float n4 = a4 + a3;
            a0 = n0; a1 = n1; a2 = n2; a3 = n3;
            if (HI) a4 = n4;
            lb = lbn; r0 = s0; r1 = s1;
        }
    };

    auto prefetch = [&](int blk, int h) {     // LO only
        unsigned d = ring_s + (unsigned)(h * (HALF * 4)) + lane * 16;
        int rs = 1 + 8 * blk;
        if (rs + 7 <= T_LEN - 1) {
            const char* s = srcb + (size_t)rs * ROWB;
            #pragma unroll
            for (int j = 0; j < 8; ++j) CP16(d + j * 512, s + (size_t)j * ROWB);
        } else {
            #pragma unroll
            for (int j = 0; j < 8; ++j) {
                int r = rs + j; if (r > T_LEN - 1) r = T_LEN - 1;
                CP16(d + j * 512, srcb + (size_t)r * ROWB);
            }
        }
        CPCOMMIT();
    };

    // ---- prologue (LO): halves 0,1,2 <- blocks 0,1,2; stage row 1 ----
    if (!HI) {
        if (lane == 0) ps->lsb[0] = 0.f;
        #pragma unroll
        for (int k = 0; k < 3; ++k) {
            unsigned d = ring_s + (unsigned)(k * (HALF * 4)) + lane * 16;
            const char* s = srcb + (size_t)(1 + 8 * k) * ROWB;
            #pragma unroll
            for (int j = 0; j < 8; ++j) CP16(d + j * 512, s + (size_t)j * ROWB);
            CPCOMMIT();
        }
        CPWAIT(2);                           // half 0 ready
        lb = ps->ring[0];
        r0 = __expf(ps->ring[e0] - lb);
        r1 = __expf(ps->ring[e1] - lb);
    }

    // ---- pipelined main loop: LO at block k, HI at block k-1 ----
    int hk = 0, hpf = 3, hj = 0;
    for (int k = 0; k < K; ++k) {
        if (!HI) {
            CPWAIT(1);                       // halves k, k+1 ready
            block8(k, hk);
            prefetch(k + 3, hpf);
            renorm(0.f);
            if (lane == 31) ps->lsb[(k + 1) & 3] = ls;
            if (++hk == NH) hk = 0;
            if (++hpf == NH) hpf = 0;
        } else if (k >= 1) {
            if (k == 1) {                    // HI's deferred initial staging
                lb = ps->ring[0];
                r0 = __expf(ps->ring[e0] - lb);
                r1 = __expf(ps->ring[e1] - lb);
            }
            block8(k - 1, hj);
            renorm(ps->lsb[k & 3]);          // clamp to next block's LO frame
            if (++hj == NH) hj = 0;
        }
        BARP(barid);
    }

    // ---- tail 1: LO remainder (R steps, writes bnd[K&3]); HI block K-1 ----
    if (!HI) {
        float* bw = ps->bnd[K & 3];
        const float* ph = ps->ring + hk * HALF;
        for (int i = 0; i < R; ++i) {
            const int o = (i + 1) * C_CLASS;
            float lbn = ph[o], w0 = ph[o + e0], w1 = ph[o + e1];
            float s0 = __expf(w0 - lbn), s1 = __expf(w1 - lbn);
            if (lane == 31) bw[i] = a3;
            float shv = __shfl_up_sync(FULLM, a3, 1);
            float nbv = shv * f;
            lsB += lb;
            float n0 = a0 + nbv;
            float n1 = r0 * fmaf(sk0, nbv, a0 + a1);
            float n2 = a2 + a1;
            float n3 = r1 * fmaf(sk1, a1, a2 + a3);
            a0 = n0; a1 = n1; a2 = n2; a3 = n3;
            lb = lbn; r0 = s0; r1 = s1;
        }
    } else if (K >= 1) {
        if (K == 1) {
            lb = ps->ring[0];
            r0 = __expf(ps->ring[e0] - lb);
            r1 = __expf(ps->ring[e1] - lb);
        }
        block8(K - 1, hj);
        renorm(ps->lsb[K & 3]);
        if (++hj == NH) hj = 0;
    }
    BARP(barid);

    // ---- tail 2: HI remainder ----
    if (HI) {
        const float* bb = ps->bnd[K & 3];
        float fw = __expf(ps->lsb[K & 3] - ls);
        const float* ph = ps->ring + hj * HALF;
        for (int i = 0; i < R; ++i) {
            const int o = (i + 1) * C_CLASS;
            float lbn = ph[o], w0 = ph[o + e0], w1 = ph[o + e1];
            float s0 = __expf(w0 - lbn), s1 = __expf(w1 - lbn);
            float shv = __shfl_up_sync(FULLM, a3, 1);
            float nbv = (lane == 0) ? bb[i] * fw : shv * f;
            lsB += lb;
            float n0 = a0 + nbv;
            float n1 = r0 * fmaf(sk0, nbv, a0 + a1);
            float n2 = a2 + a1;
            float n3 = r1 * fmaf(sk1, a1, a2 + a3);
            float n4 = a4 + a3;
            a0 = n0; a1 = n1; a2 = n2; a3 = n3; a4 = n4;
            lb = lbn; r0 = s0; r1 = s1;
        }
    }
    BARP(barid);
    if (!HI) CPWAIT(0);

    // ---- extraction: absolute log-alphas into sh ----
    const float lt = ls + lsB;
    const int sb = HI ? 128 + 4 * lane : 4 * lane;
    ps->sh[sb + 0] = (a0 > 0.f) ? __logf(a0) + lt : NEGV;
    ps->sh[sb + 1] = (a1 > 0.f) ? __logf(a1) + lt : NEGV;
    ps->sh[sb + 2] = (a2 > 0.f) ? __logf(a2) + lt : NEGV;
    ps->sh[sb + 3] = (a3 > 0.f) ? __logf(a3) + lt : NEGV;
    if (HI && lane == 31)
        ps->sh[256] = (a4 > 0.f) ? __logf(a4) + lt : NEGV;
}

__global__ void __launch_bounds__(128) ctc_kernel(
    const float* __restrict__ log_probs,
    const int*   __restrict__ targets,
    const int*   __restrict__ input_lengths,
    const int*   __restrict__ target_lengths,
    float*       __restrict__ out)
{
    __shared__ PairShared ps[2];

    const int wid  = threadIdx.x >> 5;
    const int lane = threadIdx.x & 31;
    const int pair = wid >> 1;
    const bool hi  = wid & 1;
    const int n    = blockIdx.x * 2 + pair;
    const int barid = 1 + pair;

    const float* lpn = log_probs + (size_t)n * C_CLASS;
    const int*   tg  = targets + n * S_TGT;
    const int inLen  = input_lengths[n];

    if (hi) ctc_warp<true >(&ps[pair], lpn, tg, inLen, lane, barid);
    else    ctc_warp<false>(&ps[pair], lpn, tg, inLen, lane, barid);
    BARP(barid);                              // sh complete for this pair

    if (!hi) {
        if (lane == 0) {
            int tl  = target_lengths[n];
            int idx = 2 * tl;
            float la = ps->sh ? 0.f : 0.f;    // (placeholder removed below)
            la = ps[pair].sh[idx];
            float lb2 = ps[pair].sh[idx - 1];
            float mm  = fmaxf(la, lb2);
            float lse = mm + __logf(__expf(la - mm) + __expf(lb2 - mm));
            g_partial[n] = -lse / (float)tl;
            __threadfence();
        }
        __syncwarp();
        unsigned tk = 0;
        if (lane == 0) tk = atomicAdd(&g_count, 1u);
        tk = __shfl_sync(FULLM, tk, 0);
        if (tk == NB - 1) {                   // last-arriving LO warp reduces
            __threadfence();
            float s = 0.f;
            #pragma unroll
            for (int i = 0; i < NB / 32; ++i)
                s += __ldcg(&g_partial[lane + 32 * i]);
            #pragma unroll
            for (int o = 16; o > 0; o >>= 1)
                s += __shfl_down_sync(FULLM, s, o);
            if (lane == 0) {
                out[0] = s * (1.f / (float)NB);
                g_count = 0;
            }
        }
    }
}

extern "C" void kernel_launch(void* const* d_in, const int* in_sizes, int n_in,
                              void* d_out, int out_size)
{
    const float* log_probs      = (const float*)d_in[0];
    const int*   targets        = (const int*)  d_in[1];
    const int*   input_lengths  = (const int*)  d_in[2];
    const int*   target_lengths = (const int*)  d_in[3];

    ctc_kernel<<<NB / 2, 128>>>(log_probs, targets, input_lengths,
                                target_lengths, (float*)d_out);
}